// round 1
// baseline (speedup 1.0000x reference)
#include <cuda_runtime.h>
#include <cuda_bf16.h>

#define NUM_CLASSES 1024
#define FEAT_DIM    512
#define BATCH       16384
#define ALPHA       0.5f
#define MAXC        192   // max samples tracked per class (Poisson(16) max ~40; huge margin)

// Scratch (allocation-free rule): zero-initialized at module load; kernel 2
// re-zeros g_cnt in its epilogue so every call/graph-replay sees zeros.
__device__ int g_cnt[NUM_CLASSES];
__device__ int g_slot[NUM_CLASSES * MAXC];

// Kernel 1: histogram + scatter sample indices into per-class slots.
__global__ void cl_hist_scatter(const int* __restrict__ labels) {
    int i = blockIdx.x * blockDim.x + threadIdx.x;
    if (i < BATCH) {
        int c = labels[i];
        int p = atomicAdd(&g_cnt[c], 1);
        if (p < MAXC) g_slot[c * MAXC + p] = i;
    }
}

// Kernel 2: one block per class. 128 threads, 1 float4 per thread covers the
// 512-float row. Streams the class's feature rows once, accumulates delta in
// registers, block-reduces per-sample squared distance, writes new center.
__global__ __launch_bounds__(128) void cl_main(
    const float4* __restrict__ feat,     // [BATCH][128] float4
    const float4* __restrict__ centers,  // [C][128] float4
    float*        __restrict__ result,   // [BATCH]
    float4*       __restrict__ newc)     // [C][128] float4
{
    const int c    = blockIdx.x;
    const int t    = threadIdx.x;
    const int lane = t & 31;
    const int wid  = t >> 5;

    __shared__ float red[2][4];

    const int cnt = g_cnt[c];
    const int n   = cnt < MAXC ? cnt : MAXC;

    const float4 ctr = centers[c * 128 + t];
    float4 delta = make_float4(0.f, 0.f, 0.f, 0.f);

    // Software pipeline: prefetch next sample's row while reducing current.
    int    b_next = 0;
    float4 f_next = make_float4(0.f, 0.f, 0.f, 0.f);
    if (n > 0) {
        b_next = g_slot[c * MAXC];
        f_next = feat[b_next * 128 + t];
    }

    for (int j = 0; j < n; j++) {
        const int    b = b_next;
        const float4 f = f_next;
        if (j + 1 < n) {
            b_next = g_slot[c * MAXC + j + 1];
            f_next = feat[b_next * 128 + t];
        }

        float4 d;
        d.x = ctr.x - f.x; d.y = ctr.y - f.y;
        d.z = ctr.z - f.z; d.w = ctr.w - f.w;

        delta.x += d.x; delta.y += d.y; delta.z += d.z; delta.w += d.w;

        float ss = d.x * d.x + d.y * d.y + d.z * d.z + d.w * d.w;
        #pragma unroll
        for (int o = 16; o; o >>= 1)
            ss += __shfl_xor_sync(0xffffffffu, ss, o);

        const int buf = j & 1;
        if (lane == 0) red[buf][wid] = ss;
        __syncthreads();
        if (t == 0)
            result[b] = red[buf][0] + red[buf][1] + red[buf][2] + red[buf][3];
        // No second barrier needed: red[buf] is next written at iteration j+2,
        // which is separated from this read by iteration j+1's __syncthreads.
    }

    const float s = ALPHA / (float)(cnt + 1);
    float4 nc;
    nc.x = ctr.x - delta.x * s;
    nc.y = ctr.y - delta.y * s;
    nc.z = ctr.z - delta.z * s;
    nc.w = ctr.w - delta.w * s;
    newc[c * 128 + t] = nc;

    if (t == 0) g_cnt[c] = 0;   // leave scratch zeroed for the next replay
}

extern "C" void kernel_launch(void* const* d_in, const int* in_sizes, int n_in,
                              void* d_out, int out_size) {
    const float* features = (const float*)d_in[0];   // 16384*512
    const float* centers  = (const float*)d_in[1];   // 1024*512
    const int*   labels   = (const int*)  d_in[2];   // 16384

    float* out        = (float*)d_out;
    float* result     = out;            // [16384]
    float* newcenters = out + BATCH;    // [1024*512], 64KB offset -> 16B aligned

    cl_hist_scatter<<<BATCH / 256, 256>>>(labels);

    cl_main<<<NUM_CLASSES, 128>>>(
        (const float4*)features,
        (const float4*)centers,
        result,
        (float4*)newcenters);
}

// round 3
// speedup vs baseline: 1.1830x; 1.1830x over previous
#include <cuda_runtime.h>
#include <cuda_bf16.h>

#define NUM_CLASSES 1024
#define FEAT_DIM    512
#define BATCH       16384
#define ALPHA       0.5f
#define MAXC        192   // max samples tracked per class (Poisson(16), max ~40; huge margin)

// Scratch (allocation-free rule): zero-initialized at module load; cl_main
// re-zeros g_cnt in its epilogue so every call/graph-replay sees zeros.
__device__ int g_cnt[NUM_CLASSES];
__device__ int g_slot[NUM_CLASSES * MAXC];

// Kernel 1: histogram + scatter sample indices into per-class slots.
__global__ void cl_hist_scatter(const int* __restrict__ labels) {
    int i = blockIdx.x * blockDim.x + threadIdx.x;
    if (i < BATCH) {
        int c = labels[i];
        int p = atomicAdd(&g_cnt[c], 1);
        if (p < MAXC) g_slot[c * MAXC + p] = i;
    }
}

// Kernel 2: one block per class, 4 warps. EACH WARP OWNS WHOLE SAMPLES
// (warp w -> samples w, w+4, ...). A lane covers 16 floats of the 512-row as
// 4 strided float4 loads; with a 1-deep pipeline over samples that's up to 8
// independent DRAM loads in flight per warp. Per-sample squared-distance is a
// pure warp shuffle reduce -> no __syncthreads in the hot loop. delta is
// combined across warps once per block through smem.
__global__ __launch_bounds__(128) void cl_main(
    const float4* __restrict__ feat,     // [BATCH][128] float4
    const float4* __restrict__ centers,  // [C][128] float4
    float*        __restrict__ result,   // [BATCH]
    float4*       __restrict__ newc)     // [C][128] float4
{
    const int c    = blockIdx.x;
    const int t    = threadIdx.x;
    const int lane = t & 31;
    const int wid  = t >> 5;

    __shared__ float4 sdelta[4][128];    // per-warp delta copies

    const int cnt = g_cnt[c];
    const int n   = cnt < MAXC ? cnt : MAXC;

    const float4* crow = centers + c * 128;
    const int*    slot = g_slot + c * MAXC;

    // Per-lane center chunk: float4s lane, lane+32, lane+64, lane+96.
    float4 ctr[4];
    #pragma unroll
    for (int k = 0; k < 4; k++) ctr[k] = crow[lane + 32 * k];

    float4 dl[4];
    #pragma unroll
    for (int k = 0; k < 4; k++) dl[k] = make_float4(0.f, 0.f, 0.f, 0.f);

    // Software pipeline: current sample's 4 loads + next sample's 4 in flight.
    int    b_cur = 0;
    float4 f_cur[4];
    if (wid < n) {
        b_cur = slot[wid];
        const float4* frow = feat + (size_t)b_cur * 128;
        #pragma unroll
        for (int k = 0; k < 4; k++) f_cur[k] = frow[lane + 32 * k];
    }

    for (int j = wid; j < n; j += 4) {
        // Issue next sample's loads FIRST so they overlap current compute.
        int    b_nxt = 0;
        float4 f_nxt[4];
        #pragma unroll
        for (int k = 0; k < 4; k++) f_nxt[k] = make_float4(0.f, 0.f, 0.f, 0.f);
        if (j + 4 < n) {
            b_nxt = slot[j + 4];
            const float4* frow = feat + (size_t)b_nxt * 128;
            #pragma unroll
            for (int k = 0; k < 4; k++) f_nxt[k] = frow[lane + 32 * k];
        }

        float ss = 0.f;
        #pragma unroll
        for (int k = 0; k < 4; k++) {
            float4 d;
            d.x = ctr[k].x - f_cur[k].x;
            d.y = ctr[k].y - f_cur[k].y;
            d.z = ctr[k].z - f_cur[k].z;
            d.w = ctr[k].w - f_cur[k].w;
            dl[k].x += d.x; dl[k].y += d.y; dl[k].z += d.z; dl[k].w += d.w;
            ss += d.x * d.x + d.y * d.y + d.z * d.z + d.w * d.w;
        }
        #pragma unroll
        for (int o = 16; o; o >>= 1)
            ss += __shfl_xor_sync(0xffffffffu, ss, o);
        if (lane == 0) result[b_cur] = ss;

        b_cur = b_nxt;
        #pragma unroll
        for (int k = 0; k < 4; k++) f_cur[k] = f_nxt[k];
    }

    // Cross-warp delta combine (once per block).
    #pragma unroll
    for (int k = 0; k < 4; k++) sdelta[wid][lane + 32 * k] = dl[k];
    __syncthreads();

    float4 dsum = sdelta[0][t];
    #pragma unroll
    for (int w = 1; w < 4; w++) {
        float4 v = sdelta[w][t];
        dsum.x += v.x; dsum.y += v.y; dsum.z += v.z; dsum.w += v.w;
    }

    const float s   = ALPHA / (float)(cnt + 1);
    const float4 cc = crow[t];               // L1 hit (row already resident)
    float4 nc;
    nc.x = cc.x - dsum.x * s;
    nc.y = cc.y - dsum.y * s;
    nc.z = cc.z - dsum.z * s;
    nc.w = cc.w - dsum.w * s;
    newc[c * 128 + t] = nc;

    if (t == 0) g_cnt[c] = 0;   // leave scratch zeroed for the next replay
}

extern "C" void kernel_launch(void* const* d_in, const int* in_sizes, int n_in,
                              void* d_out, int out_size) {
    const float* features = (const float*)d_in[0];   // 16384*512
    const float* centers  = (const float*)d_in[1];   // 1024*512
    const int*   labels   = (const int*)  d_in[2];   // 16384

    float* out        = (float*)d_out;
    float* result     = out;            // [16384]
    float* newcenters = out + BATCH;    // [1024*512], 64KB offset -> 16B aligned

    cl_hist_scatter<<<BATCH / 256, 256>>>(labels);

    cl_main<<<NUM_CLASSES, 128>>>(
        (const float4*)features,
        (const float4*)centers,
        result,
        (float4*)newcenters);
}